// round 5
// baseline (speedup 1.0000x reference)
#include <cuda_runtime.h>
#include <cstdint>

#define BB 8
#define NU 1024
#define NI 2048
#define NN 3072
#define DD 64
#define CE 192   // (L+1)*D concat width

// Scratch (static device allocations -- allowed)
__device__ __align__(16) float g_all_e[(size_t)BB * NN * CE];
__device__ __align__(16) float g_side[(size_t)BB * NN * DD];

// ===========================================================================
// Helpers (arch-neutral PTX, sm_80+)
// ===========================================================================
__device__ __forceinline__ uint32_t smem_u32(const void* p) {
    uint32_t a;
    asm("{ .reg .u64 t; cvta.to.shared.u64 t, %1; cvt.u32.u64 %0, t; }" : "=r"(a) : "l"(p));
    return a;
}
__device__ __forceinline__ uint32_t f2tf32(float x) {
    uint32_t h;
    asm("cvt.rna.tf32.f32 %0, %1;" : "=r"(h) : "f"(x));
    return h;
}
__device__ __forceinline__ void split3(float x, uint32_t& hi, uint32_t& lo) {
    hi = f2tf32(x);
    lo = f2tf32(x - __uint_as_float(hi));
}
__device__ __forceinline__ void mma8(float* c, const uint32_t* a, const uint32_t* b) {
    asm volatile("mma.sync.aligned.m16n8k8.row.col.f32.tf32.tf32.f32 "
                 "{%0,%1,%2,%3}, {%4,%5,%6,%7}, {%8,%9}, {%0,%1,%2,%3};"
                 : "+f"(c[0]), "+f"(c[1]), "+f"(c[2]), "+f"(c[3])
                 : "r"(a[0]), "r"(a[1]), "r"(a[2]), "r"(a[3]), "r"(b[0]), "r"(b[1]));
}
__device__ __forceinline__ void cpa16(uint32_t sdst, const void* gsrc) {
    asm volatile("cp.async.cg.shared.global [%0], [%1], 16;" :: "r"(sdst), "l"(gsrc));
}
#define CPA_COMMIT() asm volatile("cp.async.commit_group;" ::: "memory")
#define CPA_WAIT1()  asm volatile("cp.async.wait_group 1;" ::: "memory")

#define AST 36   // A smem row stride (floats): bank (4m+k) -> conflict-free frags
#define BST 72   // B smem row stride (floats): bank (8k+n) -> conflict-free frags
#define NSTG 3
#define TILE_FLOATS 2304            // 64*36 == 32*72
#define SMEM_FLOATS (NSTG * 2 * TILE_FLOATS)
#define SMEM_BYTES  (SMEM_FLOATS * 4)

// ---------------------------------------------------------------------------
// 1) Gather
// ---------------------------------------------------------------------------
__global__ void gather_kernel(const int* __restrict__ uidx, const int* __restrict__ iidx,
                              const float* __restrict__ utab, const float* __restrict__ itab) {
    int tid = blockIdx.x * blockDim.x + threadIdx.x;
    if (tid >= BB * NN * DD) return;
    int d = tid & 63;
    int r = (tid >> 6) % NN;
    int b = tid / (NN * DD);
    float v;
    if (r < NU) v = utab[(size_t)uidx[b * NU + r] * DD + d];
    else        v = itab[(size_t)iidx[b * NI + (r - NU)] * DD + d];
    g_all_e[((size_t)(b * NN + r)) * CE + d] = v;
}

// ---------------------------------------------------------------------------
// 2a) side[b] = adj[b] @ ego_l[b]  (M=3072, K=3072, N=64)
//     mma.sync 3xTF32, cp.async 3-stage pipeline, raw-fp32 smem + reg split.
//     CTA 64x64, BK=32, 8 warps (2M x 4N), warp tile 32x16.
// ---------------------------------------------------------------------------
__global__ __launch_bounds__(256) void adj_gemm_mma(const float* __restrict__ adj, int l) {
    extern __shared__ __align__(16) float sm[];
    float* As = sm;                          // [NSTG][64*AST]
    float* Bs = sm + NSTG * TILE_FLOATS;     // [NSTG][32*BST]
    uint32_t sbA = smem_u32(As), sbB = smem_u32(Bs);

    int t = threadIdx.x, lane = t & 31, wid = t >> 5;
    int b = blockIdx.y, m0 = blockIdx.x * 64;
    const float* adjb = adj + (size_t)b * NN * NN;
    const float* egob = g_all_e + (size_t)b * NN * CE + (size_t)l * DD;

    int wm = (wid & 1) * 32, wn = (wid >> 1) * 16;
    float acc[2][2][4] = {};

    // producer chunk mapping (16B chunks)
    int ar = t >> 3, ac = (t & 7) * 4;            // A: 64 rows x 8 chunks  (2 passes? no: 512 chunks, 2/thread)
    int ar2 = (t + 256) >> 3, ac2 = ((t + 256) & 7) * 4;
    int br = t >> 4, bc = (t & 15) * 4;           // B: 32 rows x 16 chunks, 2/thread
    int br2 = (t + 256) >> 4, bc2 = ((t + 256) & 15) * 4;

    const int KT = NN / 32;

    // prologue: stages 0..NSTG-2
    #pragma unroll
    for (int s = 0; s < NSTG - 1; s++) {
        int k0 = s * 32;
        uint32_t aB = sbA + s * TILE_FLOATS * 4;
        uint32_t bB = sbB + s * TILE_FLOATS * 4;
        cpa16(aB + (ar  * AST + ac ) * 4, adjb + (size_t)(m0 + ar ) * NN + k0 + ac );
        cpa16(aB + (ar2 * AST + ac2) * 4, adjb + (size_t)(m0 + ar2) * NN + k0 + ac2);
        cpa16(bB + (br  * BST + bc ) * 4, egob + (size_t)(k0 + br ) * CE + bc );
        cpa16(bB + (br2 * BST + bc2) * 4, egob + (size_t)(k0 + br2) * CE + bc2);
        CPA_COMMIT();
    }

    #pragma unroll 1
    for (int i = 0; i < KT; i++) {
        CPA_WAIT1();
        __syncthreads();

        int nx = i + NSTG - 1;
        if (nx < KT) {
            int s = nx % NSTG;
            int k0 = nx * 32;
            uint32_t aB = sbA + s * TILE_FLOATS * 4;
            uint32_t bB = sbB + s * TILE_FLOATS * 4;
            cpa16(aB + (ar  * AST + ac ) * 4, adjb + (size_t)(m0 + ar ) * NN + k0 + ac );
            cpa16(aB + (ar2 * AST + ac2) * 4, adjb + (size_t)(m0 + ar2) * NN + k0 + ac2);
            cpa16(bB + (br  * BST + bc ) * 4, egob + (size_t)(k0 + br ) * CE + bc );
            cpa16(bB + (br2 * BST + bc2) * 4, egob + (size_t)(k0 + br2) * CE + bc2);
        }
        CPA_COMMIT();

        const float* A = As + (i % NSTG) * TILE_FLOATS;
        const float* B = Bs + (i % NSTG) * TILE_FLOATS;
        #pragma unroll
        for (int kt = 0; kt < 4; kt++) {
            uint32_t aH[2][4], aL[2][4], bH[2][2], bL[2][2];
            #pragma unroll
            for (int mt = 0; mt < 2; mt++) {
                int r = wm + mt * 16 + (lane >> 2);
                int c = kt * 8 + (lane & 3);
                split3(A[r * AST + c],           aH[mt][0], aL[mt][0]);
                split3(A[(r + 8) * AST + c],     aH[mt][1], aL[mt][1]);
                split3(A[r * AST + c + 4],       aH[mt][2], aL[mt][2]);
                split3(A[(r + 8) * AST + c + 4], aH[mt][3], aL[mt][3]);
            }
            #pragma unroll
            for (int nt = 0; nt < 2; nt++) {
                int k = kt * 8 + (lane & 3);
                int n = wn + nt * 8 + (lane >> 2);
                split3(B[k * BST + n],       bH[nt][0], bL[nt][0]);
                split3(B[(k + 4) * BST + n], bH[nt][1], bL[nt][1]);
            }
            #pragma unroll
            for (int mt = 0; mt < 2; mt++)
                #pragma unroll
                for (int nt = 0; nt < 2; nt++) {
                    mma8(acc[mt][nt], aH[mt], bH[nt]);
                    mma8(acc[mt][nt], aH[mt], bL[nt]);
                    mma8(acc[mt][nt], aL[mt], bH[nt]);
                }
        }
    }

    // epilogue
    #pragma unroll
    for (int mt = 0; mt < 2; mt++) {
        int r = m0 + wm + mt * 16 + (lane >> 2);
        #pragma unroll
        for (int nt = 0; nt < 2; nt++) {
            int cc = wn + nt * 8 + (lane & 3) * 2;
            float* o = g_side + ((size_t)b * NN + r) * DD + cc;
            *(float2*)o = make_float2(acc[mt][nt][0], acc[mt][nt][1]);
            *(float2*)(o + 8 * DD) = make_float2(acc[mt][nt][2], acc[mt][nt][3]);
        }
    }
}

// ---------------------------------------------------------------------------
// 2b) Per-node layer transform
// ---------------------------------------------------------------------------
__global__ __launch_bounds__(256) void layer_kernel(const float* __restrict__ gc_w,
                                                    const float* __restrict__ gc_b,
                                                    const float* __restrict__ bi_w,
                                                    const float* __restrict__ bi_b, int l) {
    __shared__ float s_gcw[64 * 65];
    __shared__ float s_biw[64 * 65];
    __shared__ float s_side[4 * 64];
    __shared__ float s_ego[4 * 64];
    __shared__ float s_gcb[64], s_bib[64];

    int t = threadIdx.x;
    int node0 = blockIdx.x * 4;

    #pragma unroll
    for (int i = 0; i < 16; i++) {
        int idx = t + i * 256;
        int r = idx >> 6, c = idx & 63;
        s_gcw[r * 65 + c] = gc_w[l * 4096 + idx];
        s_biw[r * 65 + c] = bi_w[l * 4096 + idx];
    }
    if (t < 64) { s_gcb[t] = gc_b[l * 64 + t]; s_bib[t] = bi_b[l * 64 + t]; }
    {
        int i = t >> 6, k = t & 63;
        size_t gn = node0 + i;
        s_side[i * 64 + k] = g_side[gn * DD + k];
        s_ego[i * 64 + k]  = g_all_e[gn * CE + (size_t)l * DD + k];
    }
    __syncthreads();

    int i = t >> 6, j = t & 63;
    size_t gn = node0 + i;
    float s  = s_gcb[j];
    float bi = s_bib[j];
    #pragma unroll
    for (int k = 0; k < 64; k++) {
        float sv = s_side[i * 64 + k];
        s  += sv * s_gcw[j * 65 + k];
        bi += (s_ego[i * 64 + k] * sv) * s_biw[j * 65 + k];
    }
    s  = (s  > 0.f) ? s  : 0.01f * s;
    bi = (bi > 0.f) ? bi : 0.01f * bi;
    g_all_e[gn * CE + (size_t)(l + 1) * DD + j] = s + bi;
}

// ---------------------------------------------------------------------------
// 3) scores[b] = U @ I^T  (M=1024, N=2048, K=192) mma.sync 3xTF32 + cp.async
//    CTA 64x64, BK=32. A and B both K-major rows (stride AST).
// ---------------------------------------------------------------------------
__global__ __launch_bounds__(256) void scores_mma(float* __restrict__ out) {
    extern __shared__ __align__(16) float sm[];
    float* As = sm;
    float* Bs = sm + NSTG * TILE_FLOATS;
    uint32_t sbA = smem_u32(As), sbB = smem_u32(Bs);

    int t = threadIdx.x, lane = t & 31, wid = t >> 5;
    int b = blockIdx.z, m0 = blockIdx.y * 64, j0 = blockIdx.x * 64;

    const float* U = g_all_e + (size_t)b * NN * CE;
    const float* I = g_all_e + ((size_t)b * NN + NU) * CE;

    int wm = (wid & 1) * 32, wn = (wid >> 1) * 16;
    float acc[2][2][4] = {};

    int ar = t >> 3, ac = (t & 7) * 4;
    int ar2 = (t + 256) >> 3, ac2 = ((t + 256) & 7) * 4;

    const int KT = CE / 32;   // 6

    #pragma unroll
    for (int s = 0; s < NSTG - 1; s++) {
        int k0 = s * 32;
        uint32_t aB = sbA + s * TILE_FLOATS * 4;
        uint32_t bB = sbB + s * TILE_FLOATS * 4;
        cpa16(aB + (ar  * AST + ac ) * 4, U + (size_t)(m0 + ar ) * CE + k0 + ac );
        cpa16(aB + (ar2 * AST + ac2) * 4, U + (size_t)(m0 + ar2) * CE + k0 + ac2);
        cpa16(bB + (ar  * AST + ac ) * 4, I + (size_t)(j0 + ar ) * CE + k0 + ac );
        cpa16(bB + (ar2 * AST + ac2) * 4, I + (size_t)(j0 + ar2) * CE + k0 + ac2);
        CPA_COMMIT();
    }

    #pragma unroll 1
    for (int i = 0; i < KT; i++) {
        CPA_WAIT1();
        __syncthreads();

        int nx = i + NSTG - 1;
        if (nx < KT) {
            int s = nx % NSTG;
            int k0 = nx * 32;
            uint32_t aB = sbA + s * TILE_FLOATS * 4;
            uint32_t bB = sbB + s * TILE_FLOATS * 4;
            cpa16(aB + (ar  * AST + ac ) * 4, U + (size_t)(m0 + ar ) * CE + k0 + ac );
            cpa16(aB + (ar2 * AST + ac2) * 4, U + (size_t)(m0 + ar2) * CE + k0 + ac2);
            cpa16(bB + (ar  * AST + ac ) * 4, I + (size_t)(j0 + ar ) * CE + k0 + ac );
            cpa16(bB + (ar2 * AST + ac2) * 4, I + (size_t)(j0 + ar2) * CE + k0 + ac2);
        }
        CPA_COMMIT();

        const float* A = As + (i % NSTG) * TILE_FLOATS;
        const float* B = Bs + (i % NSTG) * TILE_FLOATS;
        #pragma unroll
        for (int kt = 0; kt < 4; kt++) {
            uint32_t aH[2][4], aL[2][4], bH[2][2], bL[2][2];
            #pragma unroll
            for (int mt = 0; mt < 2; mt++) {
                int r = wm + mt * 16 + (lane >> 2);
                int c = kt * 8 + (lane & 3);
                split3(A[r * AST + c],           aH[mt][0], aL[mt][0]);
                split3(A[(r + 8) * AST + c],     aH[mt][1], aL[mt][1]);
                split3(A[r * AST + c + 4],       aH[mt][2], aL[mt][2]);
                split3(A[(r + 8) * AST + c + 4], aH[mt][3], aL[mt][3]);
            }
            #pragma unroll
            for (int nt = 0; nt < 2; nt++) {
                int n = wn + nt * 8 + (lane >> 2);
                int c = kt * 8 + (lane & 3);
                split3(B[n * AST + c],     bH[nt][0], bL[nt][0]);
                split3(B[n * AST + c + 4], bH[nt][1], bL[nt][1]);
            }
            #pragma unroll
            for (int mt = 0; mt < 2; mt++)
                #pragma unroll
                for (int nt = 0; nt < 2; nt++) {
                    mma8(acc[mt][nt], aH[mt], bH[nt]);
                    mma8(acc[mt][nt], aH[mt], bL[nt]);
                    mma8(acc[mt][nt], aL[mt], bH[nt]);
                }
        }
    }

    #pragma unroll
    for (int mt = 0; mt < 2; mt++) {
        int r = m0 + wm + mt * 16 + (lane >> 2);
        #pragma unroll
        for (int nt = 0; nt < 2; nt++) {
            int cc = j0 + wn + nt * 8 + (lane & 3) * 2;
            float* o = out + ((size_t)b * NU + r) * NI + cc;
            *(float2*)o = make_float2(acc[mt][nt][0], acc[mt][nt][1]);
            *(float2*)(o + 8 * NI) = make_float2(acc[mt][nt][2], acc[mt][nt][3]);
        }
    }
}

// ---------------------------------------------------------------------------
// 4) In-place row log-softmax over 2048 items.
// ---------------------------------------------------------------------------
__global__ __launch_bounds__(256) void logsoftmax_kernel(float* __restrict__ out) {
    size_t row = blockIdx.x;
    float* p = out + row * NI;
    int t = threadIdx.x;

    float v[8];
    float mx = -3.4e38f;
    #pragma unroll
    for (int i = 0; i < 8; i++) { v[i] = p[t + i * 256]; mx = fmaxf(mx, v[i]); }

    __shared__ float red[8];
    #pragma unroll
    for (int o = 16; o; o >>= 1) mx = fmaxf(mx, __shfl_xor_sync(0xffffffffu, mx, o));
    if ((t & 31) == 0) red[t >> 5] = mx;
    __syncthreads();
    if (t < 32) {
        float m2 = (t < 8) ? red[t] : -3.4e38f;
        #pragma unroll
        for (int o = 4; o; o >>= 1) m2 = fmaxf(m2, __shfl_xor_sync(0xffffffffu, m2, o));
        if (t == 0) red[0] = m2;
    }
    __syncthreads();
    float bm = red[0];
    __syncthreads();

    float sum = 0.f;
    #pragma unroll
    for (int i = 0; i < 8; i++) sum += __expf(v[i] - bm);
    #pragma unroll
    for (int o = 16; o; o >>= 1) sum += __shfl_xor_sync(0xffffffffu, sum, o);
    if ((t & 31) == 0) red[t >> 5] = sum;
    __syncthreads();
    if (t < 32) {
        float s2 = (t < 8) ? red[t] : 0.f;
        #pragma unroll
        for (int o = 4; o; o >>= 1) s2 += __shfl_xor_sync(0xffffffffu, s2, o);
        if (t == 0) red[0] = s2;
    }
    __syncthreads();
    float lse = bm + logf(red[0]);

    #pragma unroll
    for (int i = 0; i < 8; i++) p[t + i * 256] = v[i] - lse;
}

// ---------------------------------------------------------------------------
extern "C" void kernel_launch(void* const* d_in, const int* in_sizes, int n_in,
                              void* d_out, int out_size) {
    const int*   uidx = (const int*)d_in[0];
    const int*   iidx = (const int*)d_in[1];
    const float* adj  = (const float*)d_in[2];
    const float* utab = (const float*)d_in[3];
    const float* itab = (const float*)d_in[4];
    const float* gc_w = (const float*)d_in[5];
    const float* gc_b = (const float*)d_in[6];
    const float* bi_w = (const float*)d_in[7];
    const float* bi_b = (const float*)d_in[8];
    float* out = (float*)d_out;

    static int attr_done = 0;
    if (!attr_done) {
        cudaFuncSetAttribute(adj_gemm_mma, cudaFuncAttributeMaxDynamicSharedMemorySize, SMEM_BYTES);
        cudaFuncSetAttribute(scores_mma,   cudaFuncAttributeMaxDynamicSharedMemorySize, SMEM_BYTES);
        attr_done = 1;
    }

    gather_kernel<<<(BB * NN * DD + 255) / 256, 256>>>(uidx, iidx, utab, itab);

    for (int l = 0; l < 2; l++) {
        dim3 g(NN / 64, BB);
        adj_gemm_mma<<<g, 256, SMEM_BYTES>>>(adj, l);
        layer_kernel<<<BB * NN / 4, 256>>>(gc_w, gc_b, bi_w, bi_b, l);
    }

    dim3 gs(NI / 64, NU / 64, BB);
    scores_mma<<<gs, 256, SMEM_BYTES>>>(out);

    logsoftmax_kernel<<<BB * NU, 256>>>(out);
}

// round 16
// speedup vs baseline: 1.0990x; 1.0990x over previous
#include <cuda_runtime.h>
#include <cstdint>

#define BB 8
#define NU 1024
#define NI 2048
#define NN 3072
#define DD 64
#define CE 192   // (L+1)*D concat width

// Scratch (static device allocations -- allowed)
__device__ __align__(16) float g_all_e[(size_t)BB * NN * CE];
__device__ __align__(16) float g_side[(size_t)BB * NN * DD];

// ===========================================================================
// TF32 helpers (arch-neutral PTX, sm_80+) -- identical to R3 (passing)
// ===========================================================================
__device__ __forceinline__ uint32_t f2tf32(float x) {
    uint32_t h;
    asm("cvt.rna.tf32.f32 %0, %1;" : "=r"(h) : "f"(x));
    return h;
}
__device__ __forceinline__ void split3(float x, uint32_t& hi, uint32_t& lo) {
    hi = f2tf32(x);
    lo = f2tf32(x - __uint_as_float(hi));
}
__device__ __forceinline__ void mma8(float* c, const uint32_t* a, const uint32_t* b) {
    asm volatile("mma.sync.aligned.m16n8k8.row.col.f32.tf32.tf32.f32 "
                 "{%0,%1,%2,%3}, {%4,%5,%6,%7}, {%8,%9}, {%0,%1,%2,%3};"
                 : "+f"(c[0]), "+f"(c[1]), "+f"(c[2]), "+f"(c[3])
                 : "r"(a[0]), "r"(a[1]), "r"(a[2]), "r"(a[3]), "r"(b[0]), "r"(b[1]));
}

#define AST 36   // A smem row stride (words): bank (4*gid+tid) -> conflict-free frags
#define BST 68   // B smem row stride (words): <=2-way (same as R3)

// ---------------------------------------------------------------------------
// 1) Gather (known good)
// ---------------------------------------------------------------------------
__global__ void gather_kernel(const int* __restrict__ uidx, const int* __restrict__ iidx,
                              const float* __restrict__ utab, const float* __restrict__ itab) {
    int tid = blockIdx.x * blockDim.x + threadIdx.x;
    if (tid >= BB * NN * DD) return;
    int d = tid & 63;
    int r = (tid >> 6) % NN;
    int b = tid / (NN * DD);
    float v;
    if (r < NU) v = utab[(size_t)uidx[b * NU + r] * DD + d];
    else        v = itab[(size_t)iidx[b * NI + (r - NU)] * DD + d];
    g_all_e[((size_t)(b * NN + r)) * CE + d] = v;
}

// ---------------------------------------------------------------------------
// 2a) side[b] = adj[b] @ ego_l[b]  (M=3072, K=3072, N=64) via mma.sync 3xTF32
//     CTA 64x64, BK=32, 4 warps (2M x 2N), warp tile 32x32.
//     R3 skeleton: LDG->split->STS, reg prefetch, two __syncthreads per k-tile.
// ---------------------------------------------------------------------------
__global__ __launch_bounds__(128) void adj_gemm_mma(const float* __restrict__ adj, int l) {
    __shared__ uint32_t Ahi[64 * AST], Alo[64 * AST];   // A: [m][k] 64x32
    __shared__ uint32_t Bhi[32 * BST], Blo[32 * BST];   // B: [k][n] 32x64

    int t = threadIdx.x, lane = t & 31, wid = t >> 5;   // wid 0..3
    int b = blockIdx.y, m0 = blockIdx.x * 64;
    const float* adjb = adj + (size_t)b * NN * NN;
    const float* egob = g_all_e + (size_t)b * NN * CE + (size_t)l * DD;

    int wm = (wid & 1) * 32, wn = (wid >> 1) * 32;
    float acc[2][4][4] = {};

    // producer mapping (128 threads)
    int ar0 = t >> 3, ak0 = (t & 7) * 4;     // A: rows ar0+16r (r=0..3), 4 k's
    int bk0 = t >> 4, bn0 = (t & 15) * 4;    // B: k-rows bk0+8r (r=0..3), 4 n's

    float4 pa[4], pb[4];
    #pragma unroll
    for (int r = 0; r < 4; r++) {
        pa[r] = *(const float4*)(adjb + (size_t)(m0 + ar0 + 16 * r) * NN + ak0);
        pb[r] = *(const float4*)(egob + (size_t)(bk0 + 8 * r) * CE + bn0);
    }

    const int KT = NN / 32;   // 96

    #pragma unroll 1
    for (int it = 0; it < KT; ++it) {
        // split + store current tile
        #pragma unroll
        for (int r = 0; r < 4; r++) {
            uint32_t h[4], lw[4];
            split3(pa[r].x, h[0], lw[0]); split3(pa[r].y, h[1], lw[1]);
            split3(pa[r].z, h[2], lw[2]); split3(pa[r].w, h[3], lw[3]);
            *(uint4*)&Ahi[(ar0 + 16 * r) * AST + ak0] = make_uint4(h[0], h[1], h[2], h[3]);
            *(uint4*)&Alo[(ar0 + 16 * r) * AST + ak0] = make_uint4(lw[0], lw[1], lw[2], lw[3]);
            split3(pb[r].x, h[0], lw[0]); split3(pb[r].y, h[1], lw[1]);
            split3(pb[r].z, h[2], lw[2]); split3(pb[r].w, h[3], lw[3]);
            *(uint4*)&Bhi[(bk0 + 8 * r) * BST + bn0] = make_uint4(h[0], h[1], h[2], h[3]);
            *(uint4*)&Blo[(bk0 + 8 * r) * BST + bn0] = make_uint4(lw[0], lw[1], lw[2], lw[3]);
        }
        __syncthreads();

        // prefetch next tile into regs (hidden under MMA phase)
        if (it + 1 < KT) {
            int k0 = (it + 1) * 32;
            #pragma unroll
            for (int r = 0; r < 4; r++) {
                pa[r] = *(const float4*)(adjb + (size_t)(m0 + ar0 + 16 * r) * NN + k0 + ak0);
                pb[r] = *(const float4*)(egob + (size_t)(k0 + bk0 + 8 * r) * CE + bn0);
            }
        }

        // MMA phase
        #pragma unroll
        for (int kt = 0; kt < 4; kt++) {
            uint32_t aH[2][4], aL[2][4], bH[4][2], bL[4][2];
            #pragma unroll
            for (int mt = 0; mt < 2; mt++) {
                int r = wm + mt * 16 + (lane >> 2);
                int c = kt * 8 + (lane & 3);
                aH[mt][0] = Ahi[r * AST + c];         aH[mt][1] = Ahi[(r + 8) * AST + c];
                aH[mt][2] = Ahi[r * AST + c + 4];     aH[mt][3] = Ahi[(r + 8) * AST + c + 4];
                aL[mt][0] = Alo[r * AST + c];         aL[mt][1] = Alo[(r + 8) * AST + c];
                aL[mt][2] = Alo[r * AST + c + 4];     aL[mt][3] = Alo[(r + 8) * AST + c + 4];
            }
            #pragma unroll
            for (int nt = 0; nt < 4; nt++) {
                int k = kt * 8 + (lane & 3);
                int n = wn + nt * 8 + (lane >> 2);
                bH[nt][0] = Bhi[k * BST + n];  bH[nt][1] = Bhi[(k + 4) * BST + n];
                bL[nt][0] = Blo[k * BST + n];  bL[nt][1] = Blo[(k + 4) * BST + n];
            }
            #pragma unroll
            for (int mt = 0; mt < 2; mt++)
                #pragma unroll
                for (int nt = 0; nt < 4; nt++) {
                    mma8(acc[mt][nt], aH[mt], bH[nt]);
                    mma8(acc[mt][nt], aH[mt], bL[nt]);
                    mma8(acc[mt][nt], aL[mt], bH[nt]);
                }
        }
        __syncthreads();
    }

    // epilogue
    #pragma unroll
    for (int mt = 0; mt < 2; mt++) {
        int r = m0 + wm + mt * 16 + (lane >> 2);
        #pragma unroll
        for (int nt = 0; nt < 4; nt++) {
            int cc = wn + nt * 8 + (lane & 3) * 2;
            float* o = g_side + ((size_t)b * NN + r) * DD + cc;
            *(float2*)o = make_float2(acc[mt][nt][0], acc[mt][nt][1]);
            *(float2*)(o + 8 * DD) = make_float2(acc[mt][nt][2], acc[mt][nt][3]);
        }
    }
}

// ---------------------------------------------------------------------------
// 2b) Per-node layer transform (known good)
// ---------------------------------------------------------------------------
__global__ __launch_bounds__(256) void layer_kernel(const float* __restrict__ gc_w,
                                                    const float* __restrict__ gc_b,
                                                    const float* __restrict__ bi_w,
                                                    const float* __restrict__ bi_b, int l) {
    __shared__ float s_gcw[64 * 65];
    __shared__ float s_biw[64 * 65];
    __shared__ float s_side[4 * 64];
    __shared__ float s_ego[4 * 64];
    __shared__ float s_gcb[64], s_bib[64];

    int t = threadIdx.x;
    int node0 = blockIdx.x * 4;

    #pragma unroll
    for (int i = 0; i < 16; i++) {
        int idx = t + i * 256;
        int r = idx >> 6, c = idx & 63;
        s_gcw[r * 65 + c] = gc_w[l * 4096 + idx];
        s_biw[r * 65 + c] = bi_w[l * 4096 + idx];
    }
    if (t < 64) { s_gcb[t] = gc_b[l * 64 + t]; s_bib[t] = bi_b[l * 64 + t]; }
    {
        int i = t >> 6, k = t & 63;
        size_t gn = node0 + i;
        s_side[i * 64 + k] = g_side[gn * DD + k];
        s_ego[i * 64 + k]  = g_all_e[gn * CE + (size_t)l * DD + k];
    }
    __syncthreads();

    int i = t >> 6, j = t & 63;
    size_t gn = node0 + i;
    float s  = s_gcb[j];
    float bi = s_bib[j];
    #pragma unroll
    for (int k = 0; k < 64; k++) {
        float sv = s_side[i * 64 + k];
        s  += sv * s_gcw[j * 65 + k];
        bi += (s_ego[i * 64 + k] * sv) * s_biw[j * 65 + k];
    }
    s  = (s  > 0.f) ? s  : 0.01f * s;
    bi = (bi > 0.f) ? bi : 0.01f * bi;
    g_all_e[gn * CE + (size_t)(l + 1) * DD + j] = s + bi;
}

// ---------------------------------------------------------------------------
// 3) scores[b] = U @ I^T  (M=1024, N=2048, K=192) via mma.sync 3xTF32
//    CTA 64x64, BK=32, 4 warps (2M x 2N), warp tile 32x32.
//    B stored [n][k] stride AST (conflict-free reads).
// ---------------------------------------------------------------------------
__global__ __launch_bounds__(128) void scores_mma(float* __restrict__ out) {
    __shared__ uint32_t Ahi[64 * AST], Alo[64 * AST];
    __shared__ uint32_t Bhi[64 * AST], Blo[64 * AST];

    int t = threadIdx.x, lane = t & 31, wid = t >> 5;
    int b = blockIdx.z, m0 = blockIdx.y * 64, j0 = blockIdx.x * 64;

    const float* U = g_all_e + (size_t)b * NN * CE;
    const float* I = g_all_e + ((size_t)b * NN + NU) * CE;

    int wm = (wid & 1) * 32, wn = (wid >> 1) * 32;
    float acc[2][4][4] = {};

    int r0 = t >> 3, kq0 = (t & 7) * 4;   // rows r0+16r, 4 k's (A and B alike)

    float4 pa[4], pb[4];
    #pragma unroll
    for (int r = 0; r < 4; r++) {
        pa[r] = *(const float4*)(U + (size_t)(m0 + r0 + 16 * r) * CE + kq0);
        pb[r] = *(const float4*)(I + (size_t)(j0 + r0 + 16 * r) * CE + kq0);
    }

    const int KT = CE / 32;   // 6

    #pragma unroll 1
    for (int it = 0; it < KT; ++it) {
        #pragma unroll
        for (int r = 0; r < 4; r++) {
            uint32_t h[4], lw[4];
            split3(pa[r].x, h[0], lw[0]); split3(pa[r].y, h[1], lw[1]);
            split3(pa[r].z, h[2], lw[2]); split3(pa[r].w, h[3], lw[3]);
            *(uint4*)&Ahi[(r0 + 16 * r) * AST + kq0] = make_uint4(h[0], h[1], h[2], h[3]);
            *(uint4*)&Alo[(r0 + 16 * r) * AST + kq0] = make_uint4(lw[0], lw[1], lw[2], lw[3]);
            split3(pb[r].x, h[0], lw[0]); split3(pb[r].y, h[1], lw[1]);
            split3(pb[r].z, h[2], lw[2]); split3(pb[r].w, h[3], lw[3]);
            *(uint4*)&Bhi[(r0 + 16 * r) * AST + kq0] = make_uint4(h[0], h[1], h[2], h[3]);
            *(uint4*)&Blo[(r0 + 16 * r) * AST + kq0] = make_uint4(lw[0], lw[1], lw[2], lw[3]);
        }
        __syncthreads();

        if (it + 1 < KT) {
            int k0 = (it + 1) * 32;
            #pragma unroll
            for (int r = 0; r < 4; r++) {
                pa[r] = *(const float4*)(U + (size_t)(m0 + r0 + 16 * r) * CE + k0 + kq0);
                pb[r] = *(const float4*)(I + (size_t)(j0 + r0 + 16 * r) * CE + k0 + kq0);
            }
        }

        #pragma unroll
        for (int kt = 0; kt < 4; kt++) {
            uint32_t aH[2][4], aL[2][4], bH[4][2], bL[4][2];
            #pragma unroll
            for (int mt = 0; mt < 2; mt++) {
                int r = wm + mt * 16 + (lane >> 2);
                int c = kt * 8 + (lane & 3);
                aH[mt][0] = Ahi[r * AST + c];         aH[mt][1] = Ahi[(r + 8) * AST + c];
                aH[mt][2] = Ahi[r * AST + c + 4];     aH[mt][3] = Ahi[(r + 8) * AST + c + 4];
                aL[mt][0] = Alo[r * AST + c];         aL[mt][1] = Alo[(r + 8) * AST + c];
                aL[mt][2] = Alo[r * AST + c + 4];     aL[mt][3] = Alo[(r + 8) * AST + c + 4];
            }
            #pragma unroll
            for (int nt = 0; nt < 4; nt++) {
                int n = wn + nt * 8 + (lane >> 2);
                int c = kt * 8 + (lane & 3);
                bH[nt][0] = Bhi[n * AST + c];  bH[nt][1] = Bhi[n * AST + c + 4];
                bL[nt][0] = Blo[n * AST + c];  bL[nt][1] = Blo[n * AST + c + 4];
            }
            #pragma unroll
            for (int mt = 0; mt < 2; mt++)
                #pragma unroll
                for (int nt = 0; nt < 4; nt++) {
                    mma8(acc[mt][nt], aH[mt], bH[nt]);
                    mma8(acc[mt][nt], aH[mt], bL[nt]);
                    mma8(acc[mt][nt], aL[mt], bH[nt]);
                }
        }
        __syncthreads();
    }

    #pragma unroll
    for (int mt = 0; mt < 2; mt++) {
        int r = m0 + wm + mt * 16 + (lane >> 2);
        #pragma unroll
        for (int nt = 0; nt < 4; nt++) {
            int cc = j0 + wn + nt * 8 + (lane & 3) * 2;
            float* o = out + ((size_t)b * NU + r) * NI + cc;
            *(float2*)o = make_float2(acc[mt][nt][0], acc[mt][nt][1]);
            *(float2*)(o + 8 * NI) = make_float2(acc[mt][nt][2], acc[mt][nt][3]);
        }
    }
}

// ---------------------------------------------------------------------------
// 4) In-place row log-softmax over 2048 items.
// ---------------------------------------------------------------------------
__global__ __launch_bounds__(256) void logsoftmax_kernel(float* __restrict__ out) {
    size_t row = blockIdx.x;
    float* p = out + row * NI;
    int t = threadIdx.x;

    float v[8];
    float mx = -3.4e38f;
    #pragma unroll
    for (int i = 0; i < 8; i++) { v[i] = p[t + i * 256]; mx = fmaxf(mx, v[i]); }

    __shared__ float red[8];
    #pragma unroll
    for (int o = 16; o; o >>= 1) mx = fmaxf(mx, __shfl_xor_sync(0xffffffffu, mx, o));
    if ((t & 31) == 0) red[t >> 5] = mx;
    __syncthreads();
    if (t < 32) {
        float m2 = (t < 8) ? red[t] : -3.4e38f;
        #pragma unroll
        for (int o = 4; o; o >>= 1) m2 = fmaxf(m2, __shfl_xor_sync(0xffffffffu, m2, o));
        if (t == 0) red[0] = m2;
    }
    __syncthreads();
    float bm = red[0];
    __syncthreads();

    float sum = 0.f;
    #pragma unroll
    for (int i = 0; i < 8; i++) sum += __expf(v[i] - bm);
    #pragma unroll
    for (int o = 16; o; o >>= 1) sum += __shfl_xor_sync(0xffffffffu, sum, o);
    if ((t & 31) == 0) red[t >> 5] = sum;
    __syncthreads();
    if (t < 32) {
        float s2 = (t < 8) ? red[t] : 0.f;
        #pragma unroll
        for (int o = 4; o; o >>= 1) s2 += __shfl_xor_sync(0xffffffffu, s2, o);
        if (t == 0) red[0] = s2;
    }
    __syncthreads();
    float lse = bm + logf(red[0]);

    #pragma unroll
    for (int i = 0; i < 8; i++) p[t + i * 256] = v[i] - lse;
}

// ---------------------------------------------------------------------------
extern "C" void kernel_launch(void* const* d_in, const int* in_sizes, int n_in,
                              void* d_out, int out_size) {
    const int*   uidx = (const int*)d_in[0];
    const int*   iidx = (const int*)d_in[1];
    const float* adj  = (const float*)d_in[2];
    const float* utab = (const float*)d_in[3];
    const float* itab = (const float*)d_in[4];
    const float* gc_w = (const float*)d_in[5];
    const float* gc_b = (const float*)d_in[6];
    const float* bi_w = (const float*)d_in[7];
    const float* bi_b = (const float*)d_in[8];
    float* out = (float*)d_out;

    gather_kernel<<<(BB * NN * DD + 255) / 256, 256>>>(uidx, iidx, utab, itab);

    for (int l = 0; l < 2; l++) {
        dim3 g(NN / 64, BB);
        adj_gemm_mma<<<g, 128>>>(adj, l);
        layer_kernel<<<BB * NN / 4, 256>>>(gc_w, gc_b, bi_w, bi_b, l);
    }

    dim3 gs(NI / 64, NU / 64, BB);
    scores_mma<<<gs, 128>>>(out);

    logsoftmax_kernel<<<BB * NU, 256>>>(out);
}